// round 1
// baseline (speedup 1.0000x reference)
#include <cuda_runtime.h>
#include <cstdint>

// Problem constants
#define NODES 64
#define FDIM  256
#define ODIM  256
#define NGRAPH 4096

// Tiling
#define BM 128      // graphs per CTA
#define BN 128      // output cols per CTA
#define KC 32       // k-chunk
#define NKC (FDIM / KC)   // 8
#define A_PAD 36    // floats per A smem row (bank-conflict-free fragment loads)
#define B_PAD 136   // floats per B smem row
#define NSTAGE 2

#define SMEM_FLOATS (NSTAGE * BM * A_PAD + NSTAGE * KC * B_PAD)
#define SMEM_BYTES  (SMEM_FLOATS * 4)

__device__ __forceinline__ uint32_t cvt_tf32(float x) {
    uint32_t r;
    asm("cvt.rna.tf32.f32 %0, %1;" : "=r"(r) : "f"(x));
    return r;
}

__device__ __forceinline__ uint32_t smem_u32(const void* p) {
    return (uint32_t)__cvta_generic_to_shared(p);
}

__device__ __forceinline__ void cp_async16(uint32_t s, const void* g) {
    asm volatile("cp.async.cg.shared.global [%0], [%1], 16;" :: "r"(s), "l"(g));
}

__global__ void linear_mlp_node_kernel(const float* __restrict__ x,
                                       const float* __restrict__ W,
                                       float* __restrict__ out) {
    extern __shared__ float smem[];
    float* sA = smem;                       // [NSTAGE][BM][A_PAD]
    float* sB = smem + NSTAGE * BM * A_PAD; // [NSTAGE][KC][B_PAD]

    const int tid   = threadIdx.x;
    const int btile = blockIdx.x;   // 0..31  (graph tiles)
    const int ntile = blockIdx.y;   // 0..1   (output col tiles)
    const int n     = blockIdx.z;   // 0..63  (node)

    const int warp = tid >> 5;
    const int lane = tid & 31;
    const int wm = warp & 3;        // 0..3 : M position (rows wm*32..wm*32+31)
    const int wn = warp >> 2;       // 0..1 : N position (cols wn*64..wn*64+63)
    const int gid = lane >> 2;      // groupID 0..7
    const int tig = lane & 3;       // thread-in-group 0..3

    const float* Wn = W + (size_t)n * FDIM * ODIM;

    // ---- async load of one k-chunk into stage s ----
    auto load_stage = [&](int stage, int kc) {
        const int k0 = kc * KC;
        float* dA = sA + stage * BM * A_PAD;
        float* dB = sB + stage * KC * B_PAD;
        // A: 128 rows x 32 floats = 1024 float4 chunks, 4 per thread
        #pragma unroll
        for (int i = 0; i < 4; i++) {
            int c = tid + i * 256;
            int row = c >> 3;          // 0..127
            int col = (c & 7) * 4;     // 0..28
            const float* g = x + ((size_t)(btile * BM + row) * NODES + n) * FDIM + k0 + col;
            cp_async16(smem_u32(dA + row * A_PAD + col), g);
        }
        // B: 32 rows x 128 floats = 1024 float4 chunks, 4 per thread
        #pragma unroll
        for (int i = 0; i < 4; i++) {
            int c = tid + i * 256;
            int row = c >> 5;          // 0..31
            int col = (c & 31) * 4;    // 0..124
            const float* g = Wn + (size_t)(k0 + row) * ODIM + ntile * BN + col;
            cp_async16(smem_u32(dB + row * B_PAD + col), g);
        }
        asm volatile("cp.async.commit_group;");
    };

    float acc[2][8][4];
    #pragma unroll
    for (int mt = 0; mt < 2; mt++)
        #pragma unroll
        for (int nt = 0; nt < 8; nt++)
            #pragma unroll
            for (int r = 0; r < 4; r++)
                acc[mt][nt][r] = 0.0f;

    load_stage(0, 0);

    for (int kc = 0; kc < NKC; kc++) {
        const int stage = kc & 1;
        if (kc + 1 < NKC) {
            load_stage((kc + 1) & 1, kc + 1);
            asm volatile("cp.async.wait_group 1;");
        } else {
            asm volatile("cp.async.wait_group 0;");
        }
        __syncthreads();

        const float* cA = sA + stage * BM * A_PAD + (wm * 32) * A_PAD;
        const float* cB = sB + stage * KC * B_PAD + wn * 64;

        #pragma unroll
        for (int s = 0; s < 4; s++) {           // 4 k-steps of 8
            uint32_t a[2][4], b[8][2];
            #pragma unroll
            for (int mt = 0; mt < 2; mt++) {
                const float* p = cA + (mt * 16 + gid) * A_PAD + s * 8 + tig;
                a[mt][0] = cvt_tf32(p[0]);
                a[mt][1] = cvt_tf32(p[8 * A_PAD]);
                a[mt][2] = cvt_tf32(p[4]);
                a[mt][3] = cvt_tf32(p[8 * A_PAD + 4]);
            }
            #pragma unroll
            for (int nt = 0; nt < 8; nt++) {
                const float* p = cB + (s * 8 + tig) * B_PAD + nt * 8 + gid;
                b[nt][0] = cvt_tf32(p[0]);
                b[nt][1] = cvt_tf32(p[4 * B_PAD]);
            }
            #pragma unroll
            for (int mt = 0; mt < 2; mt++) {
                #pragma unroll
                for (int nt = 0; nt < 8; nt++) {
                    asm volatile(
                        "mma.sync.aligned.m16n8k8.row.col.f32.tf32.tf32.f32 "
                        "{%0,%1,%2,%3}, {%4,%5,%6,%7}, {%8,%9}, {%0,%1,%2,%3};"
                        : "+f"(acc[mt][nt][0]), "+f"(acc[mt][nt][1]),
                          "+f"(acc[mt][nt][2]), "+f"(acc[mt][nt][3])
                        : "r"(a[mt][0]), "r"(a[mt][1]), "r"(a[mt][2]), "r"(a[mt][3]),
                          "r"(b[nt][0]), "r"(b[nt][1]));
                }
            }
        }
        __syncthreads();
    }

    // ---- epilogue: scale by 1/sqrt(F) = 1/16, write fp32 ----
    const float scale = 0.0625f;
    #pragma unroll
    for (int mt = 0; mt < 2; mt++) {
        #pragma unroll
        for (int nt = 0; nt < 8; nt++) {
            int g0  = btile * BM + wm * 32 + mt * 16 + gid;      // graph index (rows gid, gid+8)
            int col = ntile * BN + wn * 64 + nt * 8 + tig * 2;
            float2 v0 = make_float2(acc[mt][nt][0] * scale, acc[mt][nt][1] * scale);
            float2 v1 = make_float2(acc[mt][nt][2] * scale, acc[mt][nt][3] * scale);
            size_t r0 = ((size_t)g0 * NODES + n) * ODIM + col;
            size_t r1 = ((size_t)(g0 + 8) * NODES + n) * ODIM + col;
            *reinterpret_cast<float2*>(out + r0) = v0;
            *reinterpret_cast<float2*>(out + r1) = v1;
        }
    }
}

extern "C" void kernel_launch(void* const* d_in, const int* in_sizes, int n_in,
                              void* d_out, int out_size) {
    const float* x = (const float*)d_in[0];
    // d_in[1] = batch indices (int64) — implied by row layout, unused
    const float* W = (const float*)d_in[2];
    float* out = (float*)d_out;

    cudaFuncSetAttribute(linear_mlp_node_kernel,
                         cudaFuncAttributeMaxDynamicSharedMemorySize, SMEM_BYTES);

    dim3 grid(NGRAPH / BM, ODIM / BN, NODES);   // (32, 2, 64)
    linear_mlp_node_kernel<<<grid, 256, SMEM_BYTES>>>(x, W, out);
}

// round 5
// speedup vs baseline: 1.2120x; 1.2120x over previous
#include <cuda_runtime.h>
#include <cstdint>

// out[(b*64+n), :] = x[(b*64+n), :] @ W[n] / 16
// x: [4096*64, 256] f32, W: [64, 256, 256] f32, out: [4096*64, 256] f32
#define NODES   64
#define FDIM    256
#define ODIM    256
#define NGRAPH  4096

#define BM 128          // graphs per CTA
#define BN 128          // output cols per CTA
#define KC 32           // k-chunk
#define NKC (FDIM / KC) // 8
#define A_PAD 36        // floats per A smem row
#define NSTAGE 2

#define A_STAGE_FLOATS (BM * A_PAD)     // 4608
#define B_STAGE_FLOATS (KC * BN)        // 4096 floats = 1024 float4 (CTA's 128 cols)
#define SMEM_FLOATS (NSTAGE * (A_STAGE_FLOATS + B_STAGE_FLOATS))
#define SMEM_BYTES  (SMEM_FLOATS * 4)   // 69632

// packed W: per (node, chunk): 2048 float4 = 32 k x 256 cols
#define CHUNK_F4 2048

__device__ __forceinline__ uint32_t smem_u32(const void* p) {
    return (uint32_t)__cvta_generic_to_shared(p);
}
__device__ __forceinline__ void cp_async16(uint32_t s, const void* g) {
    asm volatile("cp.async.cg.shared.global [%0], [%1], 16;" :: "r"(s), "l"(g));
}

// Packed, pre-scaled, tf32-rounded W fragments:
// layout [n][chunk][wn(0..3)][s(0..3)][j(0..3)][lane(0..31)] as float4:
//   {W'(k0,o0), W'(k0+4,o0), W'(k0,o1), W'(k0+4,o1)}
//   k0 = chunk*32 + s*8 + tig, o0 = wn*64 + 2*j*8 + gid, o1 = o0 + 8
//   gid = lane>>2, tig = lane&3
__device__ float4 Wp_g[NODES * NKC * CHUNK_F4];   // 16 MB

__global__ void pack_w_kernel(const float* __restrict__ W) {
    __shared__ float sw[KC * ODIM];     // 32 rows x 256 cols = 32KB
    const int n = blockIdx.y;
    const int chunk = blockIdx.x;
    const int tid = threadIdx.x;
    const float4* src = (const float4*)(W + (size_t)n * FDIM * ODIM + (size_t)chunk * KC * ODIM);
    float4* dst = (float4*)sw;
    #pragma unroll
    for (int i = 0; i < 8; i++)
        dst[tid + i * 256] = src[tid + i * 256];
    __syncthreads();

    // scale = 1/16 * (1 + 2^-11): compensates HW tf32 truncation bias on x
    const float sc = 0.0625f * 1.00048828125f;
    float4* outp = Wp_g + ((size_t)n * NKC + chunk) * CHUNK_F4;
    #pragma unroll
    for (int i = 0; i < 8; i++) {
        int c = tid + i * 256;          // 0..2047
        int lane = c & 31;
        int j    = (c >> 5) & 3;
        int s    = (c >> 7) & 3;
        int wn   = c >> 9;              // 0..3
        int gid = lane >> 2, tig = lane & 3;
        int k  = s * 8 + tig;
        int o0 = wn * 64 + 2 * j * 8 + gid;
        float4 v;
        uint32_t u;
        float t;
        t = sw[k * ODIM + o0] * sc;
        asm("cvt.rna.tf32.f32 %0, %1;" : "=r"(u) : "f"(t)); v.x = __uint_as_float(u);
        t = sw[(k + 4) * ODIM + o0] * sc;
        asm("cvt.rna.tf32.f32 %0, %1;" : "=r"(u) : "f"(t)); v.y = __uint_as_float(u);
        t = sw[k * ODIM + o0 + 8] * sc;
        asm("cvt.rna.tf32.f32 %0, %1;" : "=r"(u) : "f"(t)); v.z = __uint_as_float(u);
        t = sw[(k + 4) * ODIM + o0 + 8] * sc;
        asm("cvt.rna.tf32.f32 %0, %1;" : "=r"(u) : "f"(t)); v.w = __uint_as_float(u);
        outp[c] = v;
    }
}

__global__ void __launch_bounds__(256, 2)
linear_mlp_node_kernel(const float* __restrict__ x, float* __restrict__ out) {
    extern __shared__ float smem[];
    float* sA = smem;                                  // [NSTAGE][BM][A_PAD]
    float* sB = smem + NSTAGE * A_STAGE_FLOATS;        // [NSTAGE][1024 float4]

    const int tid   = threadIdx.x;
    const int btile = blockIdx.x;   // 0..31
    const int ntile = blockIdx.y;   // 0..1
    const int n     = blockIdx.z;   // 0..63

    const int warp = tid >> 5;
    const int lane = tid & 31;
    const int wm = warp & 3;        // rows wm*32..+31
    const int wn = warp >> 2;       // cols wn*64..+63 (within this CTA's 128)
    const int gid = lane >> 2;
    const int tig = lane & 3;

    const float4* WpN = Wp_g + (size_t)n * NKC * CHUNK_F4;

    auto load_stage = [&](int stage, int kc) {
        const int k0 = kc * KC;
        float* dA = sA + stage * A_STAGE_FLOATS;
        // A: 128 rows x 32 floats = 1024 x 16B, 4 per thread
        #pragma unroll
        for (int i = 0; i < 4; i++) {
            int c = tid + i * 256;
            int row = c >> 3, ch = c & 7;
            const float* g = x + ((size_t)(btile * BM + row) * NODES + n) * FDIM + k0 + ch * 4;
            cp_async16(smem_u32(dA + row * A_PAD + ch * 4), g);
        }
        // B: the two 512-float4 wn-slabs covering this CTA's 128 cols, contiguous
        const float4* gB = WpN + (size_t)kc * CHUNK_F4 + (size_t)ntile * 1024;
        float4* dB = (float4*)(sB + stage * B_STAGE_FLOATS);
        #pragma unroll
        for (int i = 0; i < 4; i++) {
            int c = tid + i * 256;
            cp_async16(smem_u32(dB + c), gB + c);
        }
        asm volatile("cp.async.commit_group;" ::: "memory");
    };

    float acc[2][8][4];
    #pragma unroll
    for (int mt = 0; mt < 2; mt++)
        #pragma unroll
        for (int nt = 0; nt < 8; nt++)
            #pragma unroll
            for (int r = 0; r < 4; r++)
                acc[mt][nt][r] = 0.0f;

    load_stage(0, 0);

    for (int kc = 0; kc < NKC; kc++) {
        const int stage = kc & 1;
        if (kc + 1 < NKC) {
            load_stage((kc + 1) & 1, kc + 1);
            asm volatile("cp.async.wait_group 1;" ::: "memory");
        } else {
            asm volatile("cp.async.wait_group 0;" ::: "memory");
        }
        __syncthreads();

        const float* cA = sA + stage * A_STAGE_FLOATS + (wm * 32) * A_PAD;
        // B fragments for this warp: [wn][s][j][lane] float4
        const float4* cB = (const float4*)(sB + stage * B_STAGE_FLOATS) + wn * 512 + lane;

        #pragma unroll
        for (int s = 0; s < 4; s++) {
            uint32_t a[2][4];
            float4 b[4];
            #pragma unroll
            for (int mt = 0; mt < 2; mt++) {
                const float* p = cA + (mt * 16 + gid) * A_PAD + s * 8 + tig;
                a[mt][0] = __float_as_uint(p[0]);
                a[mt][1] = __float_as_uint(p[8 * A_PAD]);
                a[mt][2] = __float_as_uint(p[4]);
                a[mt][3] = __float_as_uint(p[8 * A_PAD + 4]);
            }
            #pragma unroll
            for (int j = 0; j < 4; j++)
                b[j] = cB[(s * 4 + j) * 32];

            #pragma unroll
            for (int mt = 0; mt < 2; mt++) {
                #pragma unroll
                for (int j = 0; j < 4; j++) {
                    asm volatile(
                        "mma.sync.aligned.m16n8k8.row.col.f32.tf32.tf32.f32 "
                        "{%0,%1,%2,%3}, {%4,%5,%6,%7}, {%8,%9}, {%0,%1,%2,%3};"
                        : "+f"(acc[mt][2 * j][0]), "+f"(acc[mt][2 * j][1]),
                          "+f"(acc[mt][2 * j][2]), "+f"(acc[mt][2 * j][3])
                        : "r"(a[mt][0]), "r"(a[mt][1]), "r"(a[mt][2]), "r"(a[mt][3]),
                          "r"(__float_as_uint(b[j].x)), "r"(__float_as_uint(b[j].y)));
                    asm volatile(
                        "mma.sync.aligned.m16n8k8.row.col.f32.tf32.tf32.f32 "
                        "{%0,%1,%2,%3}, {%4,%5,%6,%7}, {%8,%9}, {%0,%1,%2,%3};"
                        : "+f"(acc[mt][2 * j + 1][0]), "+f"(acc[mt][2 * j + 1][1]),
                          "+f"(acc[mt][2 * j + 1][2]), "+f"(acc[mt][2 * j + 1][3])
                        : "r"(a[mt][0]), "r"(a[mt][1]), "r"(a[mt][2]), "r"(a[mt][3]),
                          "r"(__float_as_uint(b[j].z)), "r"(__float_as_uint(b[j].w)));
                }
            }
        }
        __syncthreads();
    }

    // epilogue (scale already folded into W)
    #pragma unroll
    for (int mt = 0; mt < 2; mt++) {
        #pragma unroll
        for (int nt = 0; nt < 8; nt++) {
            int g0  = btile * BM + wm * 32 + mt * 16 + gid;
            int col = ntile * BN + wn * 64 + nt * 8 + tig * 2;
            size_t r0 = ((size_t)g0 * NODES + n) * ODIM + col;
            size_t r1 = ((size_t)(g0 + 8) * NODES + n) * ODIM + col;
            *reinterpret_cast<float2*>(out + r0) = make_float2(acc[mt][nt][0], acc[mt][nt][1]);
            *reinterpret_cast<float2*>(out + r1) = make_float2(acc[mt][nt][2], acc[mt][nt][3]);
        }
    }
}

extern "C" void kernel_launch(void* const* d_in, const int* in_sizes, int n_in,
                              void* d_out, int out_size) {
    const float* x = (const float*)d_in[0];
    // d_in[1] = batch indices (int64) — implied by layout, unused
    const float* W = (const float*)d_in[2];
    float* out = (float*)d_out;

    pack_w_kernel<<<dim3(NKC, NODES), 256>>>(W);

    cudaFuncSetAttribute(linear_mlp_node_kernel,
                         cudaFuncAttributeMaxDynamicSharedMemorySize, SMEM_BYTES);
    dim3 grid(NGRAPH / BM, ODIM / BN, NODES);   // (32, 2, 64)
    linear_mlp_node_kernel<<<grid, 256, SMEM_BYTES>>>(x, out);
}

// round 6
// speedup vs baseline: 1.3079x; 1.0791x over previous
#include <cuda_runtime.h>
#include <cstdint>

// out[(b*64+n), :] = x[(b*64+n), :] @ W[n] / 16
// x: [4096*64, 256] f32, W: [64, 256, 256] f32, out: [4096*64, 256] f32
#define NODES   64
#define FDIM    256
#define ODIM    256
#define NGRAPH  4096

#define BM 128          // graphs per CTA
#define BN 128          // output cols per CTA
#define KC 32           // k-chunk
#define NKC (FDIM / KC) // 8
#define A_PAD 36        // floats per A smem row
#define NSTAGE 2
#define NTHREADS 128    // 4 warps, each owns a 64x64 warp tile

#define A_STAGE_FLOATS (BM * A_PAD)     // 4608
#define B_STAGE_FLOATS (KC * BN)        // 4096 floats = 1024 float4
#define SMEM_FLOATS (NSTAGE * (A_STAGE_FLOATS + B_STAGE_FLOATS))
#define SMEM_BYTES  (SMEM_FLOATS * 4)   // 69632

// packed W: per (node, chunk): 2048 float4 = 32 k x 256 cols
#define CHUNK_F4 2048

__device__ __forceinline__ uint32_t smem_u32(const void* p) {
    return (uint32_t)__cvta_generic_to_shared(p);
}
__device__ __forceinline__ void cp_async16(uint32_t s, const void* g) {
    asm volatile("cp.async.cg.shared.global [%0], [%1], 16;" :: "r"(s), "l"(g));
}

// Packed, pre-scaled, tf32-rounded W fragments (layout identical to R5):
// [n][chunk][wn(0..3)][s(0..3)][j(0..3)][lane(0..31)] as float4:
//   {W'(k0,o0), W'(k0+4,o0), W'(k0,o1), W'(k0+4,o1)}
//   k0 = chunk*32 + s*8 + tig, o0 = wn*64 + 2*j*8 + gid, o1 = o0 + 8
__device__ float4 Wp_g[NODES * NKC * CHUNK_F4];   // 16 MB

__global__ void pack_w_kernel(const float* __restrict__ W) {
    __shared__ float sw[KC * ODIM];     // 32 x 256 = 32KB
    const int n = blockIdx.y;
    const int chunk = blockIdx.x;
    const int tid = threadIdx.x;
    const float4* src = (const float4*)(W + (size_t)n * FDIM * ODIM + (size_t)chunk * KC * ODIM);
    float4* dst = (float4*)sw;
    #pragma unroll
    for (int i = 0; i < 8; i++)
        dst[tid + i * 256] = src[tid + i * 256];
    __syncthreads();

    // scale = 1/16 * (1 + 2^-11): compensates HW tf32 truncation bias on x
    const float sc = 0.0625f * 1.00048828125f;
    float4* outp = Wp_g + ((size_t)n * NKC + chunk) * CHUNK_F4;
    #pragma unroll
    for (int i = 0; i < 8; i++) {
        int c = tid + i * 256;          // 0..2047
        int lane = c & 31;
        int j    = (c >> 5) & 3;
        int s    = (c >> 7) & 3;
        int wn   = c >> 9;              // 0..3
        int gid = lane >> 2, tig = lane & 3;
        int k  = s * 8 + tig;
        int o0 = wn * 64 + 2 * j * 8 + gid;
        float4 v;
        uint32_t u;
        float t;
        t = sw[k * ODIM + o0] * sc;
        asm("cvt.rna.tf32.f32 %0, %1;" : "=r"(u) : "f"(t)); v.x = __uint_as_float(u);
        t = sw[(k + 4) * ODIM + o0] * sc;
        asm("cvt.rna.tf32.f32 %0, %1;" : "=r"(u) : "f"(t)); v.y = __uint_as_float(u);
        t = sw[k * ODIM + o0 + 8] * sc;
        asm("cvt.rna.tf32.f32 %0, %1;" : "=r"(u) : "f"(t)); v.z = __uint_as_float(u);
        t = sw[(k + 4) * ODIM + o0 + 8] * sc;
        asm("cvt.rna.tf32.f32 %0, %1;" : "=r"(u) : "f"(t)); v.w = __uint_as_float(u);
        outp[c] = v;
    }
}

__global__ void __launch_bounds__(NTHREADS, 2)
linear_mlp_node_kernel(const float* __restrict__ x, float* __restrict__ out) {
    extern __shared__ float smem[];
    float* sA = smem;                                  // [NSTAGE][BM][A_PAD]
    float* sB = smem + NSTAGE * A_STAGE_FLOATS;        // [NSTAGE][1024 float4]

    const int tid   = threadIdx.x;
    const int btile = blockIdx.x;   // 0..31
    const int ntile = blockIdx.y;   // 0..1
    const int n     = blockIdx.z;   // 0..63

    const int warp = tid >> 5;      // 0..3
    const int lane = tid & 31;
    const int wm = warp & 1;        // rows wm*64..+63
    const int wn = warp >> 1;       // cols wn*64..+63 (within this CTA's 128)
    const int gid = lane >> 2;
    const int tig = lane & 3;

    const float4* WpN = Wp_g + (size_t)n * NKC * CHUNK_F4;

    auto load_stage = [&](int stage, int kc) {
        const int k0 = kc * KC;
        float* dA = sA + stage * A_STAGE_FLOATS;
        // A: 128 rows x 32 floats = 1024 x 16B, 8 per thread
        #pragma unroll
        for (int i = 0; i < 8; i++) {
            int c = tid + i * NTHREADS;
            int row = c >> 3, ch = c & 7;
            const float* g = x + ((size_t)(btile * BM + row) * NODES + n) * FDIM + k0 + ch * 4;
            cp_async16(smem_u32(dA + row * A_PAD + ch * 4), g);
        }
        // B: two contiguous 512-float4 wn-slabs covering this CTA's 128 cols
        const float4* gB = WpN + (size_t)kc * CHUNK_F4 + (size_t)ntile * 1024;
        float4* dB = (float4*)(sB + stage * B_STAGE_FLOATS);
        #pragma unroll
        for (int i = 0; i < 8; i++) {
            int c = tid + i * NTHREADS;
            cp_async16(smem_u32(dB + c), gB + c);
        }
        asm volatile("cp.async.commit_group;" ::: "memory");
    };

    float acc[4][8][4];
    #pragma unroll
    for (int mt = 0; mt < 4; mt++)
        #pragma unroll
        for (int nt = 0; nt < 8; nt++)
            #pragma unroll
            for (int r = 0; r < 4; r++)
                acc[mt][nt][r] = 0.0f;

    load_stage(0, 0);

    for (int kc = 0; kc < NKC; kc++) {
        const int stage = kc & 1;
        if (kc + 1 < NKC) {
            load_stage((kc + 1) & 1, kc + 1);
            asm volatile("cp.async.wait_group 1;" ::: "memory");
        } else {
            asm volatile("cp.async.wait_group 0;" ::: "memory");
        }
        __syncthreads();

        const float* cA = sA + stage * A_STAGE_FLOATS + (wm * 64) * A_PAD;
        // B fragments for this warp: [wn][s][j][lane] float4
        const float4* cB = (const float4*)(sB + stage * B_STAGE_FLOATS) + wn * 512 + lane;

        #pragma unroll
        for (int s = 0; s < 4; s++) {
            uint32_t a[4][4];
            float4 b[4];
            #pragma unroll
            for (int mt = 0; mt < 4; mt++) {
                const float* p = cA + (mt * 16 + gid) * A_PAD + s * 8 + tig;
                a[mt][0] = __float_as_uint(p[0]);
                a[mt][1] = __float_as_uint(p[8 * A_PAD]);
                a[mt][2] = __float_as_uint(p[4]);
                a[mt][3] = __float_as_uint(p[8 * A_PAD + 4]);
            }
            #pragma unroll
            for (int j = 0; j < 4; j++)
                b[j] = cB[(s * 4 + j) * 32];

            #pragma unroll
            for (int mt = 0; mt < 4; mt++) {
                #pragma unroll
                for (int j = 0; j < 4; j++) {
                    asm volatile(
                        "mma.sync.aligned.m16n8k8.row.col.f32.tf32.tf32.f32 "
                        "{%0,%1,%2,%3}, {%4,%5,%6,%7}, {%8,%9}, {%0,%1,%2,%3};"
                        : "+f"(acc[mt][2 * j][0]), "+f"(acc[mt][2 * j][1]),
                          "+f"(acc[mt][2 * j][2]), "+f"(acc[mt][2 * j][3])
                        : "r"(a[mt][0]), "r"(a[mt][1]), "r"(a[mt][2]), "r"(a[mt][3]),
                          "r"(__float_as_uint(b[j].x)), "r"(__float_as_uint(b[j].y)));
                    asm volatile(
                        "mma.sync.aligned.m16n8k8.row.col.f32.tf32.tf32.f32 "
                        "{%0,%1,%2,%3}, {%4,%5,%6,%7}, {%8,%9}, {%0,%1,%2,%3};"
                        : "+f"(acc[mt][2 * j + 1][0]), "+f"(acc[mt][2 * j + 1][1]),
                          "+f"(acc[mt][2 * j + 1][2]), "+f"(acc[mt][2 * j + 1][3])
                        : "r"(a[mt][0]), "r"(a[mt][1]), "r"(a[mt][2]), "r"(a[mt][3]),
                          "r"(__float_as_uint(b[j].z)), "r"(__float_as_uint(b[j].w)));
                }
            }
        }
        __syncthreads();
    }

    // epilogue (scale already folded into W)
    #pragma unroll
    for (int mt = 0; mt < 4; mt++) {
        #pragma unroll
        for (int nt = 0; nt < 8; nt++) {
            int g0  = btile * BM + wm * 64 + mt * 16 + gid;
            int col = ntile * BN + wn * 64 + nt * 8 + tig * 2;
            size_t r0 = ((size_t)g0 * NODES + n) * ODIM + col;
            size_t r1 = ((size_t)(g0 + 8) * NODES + n) * ODIM + col;
            *reinterpret_cast<float2*>(out + r0) = make_float2(acc[mt][nt][0], acc[mt][nt][1]);
            *reinterpret_cast<float2*>(out + r1) = make_float2(acc[mt][nt][2], acc[mt][nt][3]);
        }
    }
}

extern "C" void kernel_launch(void* const* d_in, const int* in_sizes, int n_in,
                              void* d_out, int out_size) {
    const float* x = (const float*)d_in[0];
    // d_in[1] = batch indices (int64) — implied by layout, unused
    const float* W = (const float*)d_in[2];
    float* out = (float*)d_out;

    pack_w_kernel<<<dim3(NKC, NODES), 256>>>(W);

    cudaFuncSetAttribute(linear_mlp_node_kernel,
                         cudaFuncAttributeMaxDynamicSharedMemorySize, SMEM_BYTES);
    dim3 grid(NGRAPH / BM, ODIM / BN, NODES);   // (32, 2, 64)
    linear_mlp_node_kernel<<<grid, NTHREADS, SMEM_BYTES>>>(x, out);
}